// round 8
// baseline (speedup 1.0000x reference)
#include <cuda_runtime.h>
#include <cstdint>
#include <cstddef>

#define DEV_INLINE __device__ __forceinline__

constexpr int D        = 512;       // feature dim
constexpr int FV       = 12;        // video frames
constexpr int THREADS  = 256;       // 8 warps
constexpr int RPW      = 5;         // text rows per warp (single pass)
constexpr int ROWS_CTA = 8 * RPW;   // 40 rows per CTA

// scratch (allocation-free: __device__ globals)
__device__ float g_part_min[4096];
__device__ float g_part_max[4096];
__device__ float g_rowval[1024];
__device__ float g_diagval[1024];
__device__ unsigned int g_done = 0;

DEV_INLINE unsigned long long ffma2(unsigned long long a, unsigned long long b,
                                    unsigned long long c) {
    unsigned long long d;
    asm("fma.rn.f32x2 %0, %1, %2, %3;" : "=l"(d) : "l"(a), "l"(b), "l"(c));
    return d;
}

DEV_INLINE float hsum2(unsigned long long v) {
    float lo, hi;
    asm("mov.b64 {%0, %1}, %2;" : "=f"(lo), "=f"(hi) : "l"(v));
    return lo + hi;
}

DEV_INLINE void cp_async16(uint32_t smem_addr, const void* gptr) {
    asm volatile("cp.async.cg.shared.global [%0], [%1], 16;"
                 :: "r"(smem_addr), "l"(gptr));
}
#define CP_COMMIT()  asm volatile("cp.async.commit_group;")
#define CP_WAIT0()   asm volatile("cp.async.wait_group 0;" ::: "memory")

// ---------------------------------------------------------------------------
// Kernel 1: per-(sample, chunk) min/max cosine over (40 text rows) x (12 video).
// Video staged in shared (cp.async); text read directly via LDG.128 with
// 1-step register prefetch (one 128B line per warp-row-step).
// Epilogue: last-arriving CTA (atomic counter) reduces all partials ONCE,
// writes per-row rv/dv arrays, and resets the counter (graph-replay safe).
// Min/max reductions are order-independent -> deterministic output.
// ---------------------------------------------------------------------------
__global__ void __launch_bounds__(THREADS, 2)
sample_minmax_kernel(const float* __restrict__ text,
                     const float* __restrict__ video,
                     int T, int chunks)
{
    __shared__ float sv[FV * D];          // 24 KB video tile
    __shared__ float s_vinv[FV];
    __shared__ float s_wmin[8], s_wmax[8];
    __shared__ float red_mn[256], red_mx[256];
    __shared__ unsigned int s_last;

    const int b     = blockIdx.x / chunks;
    const int chunk = blockIdx.x % chunks;
    const int tid   = threadIdx.x;
    const int warp  = tid >> 5;
    const int lane  = tid & 31;
    const int fg    = lane >> 3;   // 0..3 : which group of 3 video rows
    const int dl    = lane & 7;    // 0..7 : which slice of D

    const char* vsrc = reinterpret_cast<const char*>(video + (size_t)b * FV * D);
    const float* tb  = text + (size_t)b * (size_t)T * D;
    const int base   = chunk * ROWS_CTA;

    // ---- issue video staging (one cp.async group) ----
    {
        uint32_t svb = (uint32_t)__cvta_generic_to_shared(sv);
        #pragma unroll
        for (int i = tid; i < FV * (D / 4); i += THREADS)
            cp_async16(svb + i * 16, vsrc + i * 16);
        CP_COMMIT();
    }

    // ---- text row pointers (clamped duplicates are harmless for min/max) ----
    const float* trp[RPW];
    #pragma unroll
    for (int r = 0; r < RPW; r++) {
        int tt = base + warp * RPW + r; if (tt > T - 1) tt = T - 1;
        trp[r] = tb + (size_t)tt * D;
    }

    // ---- prime step-0 text loads (independent of smem; hide behind norms) ----
    ulonglong2 tv[RPW];
    #pragma unroll
    for (int r = 0; r < RPW; r++)
        tv[r] = *reinterpret_cast<const ulonglong2*>(trp[r] + dl * 4);

    CP_WAIT0();
    __syncthreads();

    // ---- inverse norms of the 12 video rows (from shared) ----
    for (int f = warp; f < FV; f += 8) {
        float s = 0.f;
        #pragma unroll
        for (int c = lane; c < D / 4; c += 32) {
            float4 x = *reinterpret_cast<const float4*>(&sv[f * D + c * 4]);
            s += x.x * x.x + x.y * x.y + x.z * x.z + x.w * x.w;
        }
        #pragma unroll
        for (int o = 16; o > 0; o >>= 1) s += __shfl_xor_sync(0xffffffffu, s, o);
        if (lane == 0) s_vinv[f] = rsqrtf(s);
    }
    __syncthreads();

    const int f0 = fg * 3;
    const float vinv0 = s_vinv[f0 + 0];
    const float vinv1 = s_vinv[f0 + 1];
    const float vinv2 = s_vinv[f0 + 2];
    const float* svp0 = &sv[(f0 + 0) * D];
    const float* svp1 = &sv[(f0 + 1) * D];
    const float* svp2 = &sv[(f0 + 2) * D];

    unsigned long long acc[RPW][3];
    unsigned long long nrm[RPW];
    #pragma unroll
    for (int r = 0; r < RPW; r++) {
        acc[r][0] = 0ull; acc[r][1] = 0ull; acc[r][2] = 0ull; nrm[r] = 0ull;
    }

    // ---- mainloop: video from shared, text from global w/ 1-step prefetch ----
    #pragma unroll
    for (int s = 0; s < 16; s++) {
        const int off = (dl + 8 * s) * 4;                  // float offset, 16B aligned
        ulonglong2 tnx[RPW];
        if (s < 15) {
            const int noff = (dl + 8 * (s + 1)) * 4;
            #pragma unroll
            for (int r = 0; r < RPW; r++)
                tnx[r] = *reinterpret_cast<const ulonglong2*>(trp[r] + noff);
        }
        ulonglong2 v0 = *reinterpret_cast<const ulonglong2*>(svp0 + off);
        ulonglong2 v1 = *reinterpret_cast<const ulonglong2*>(svp1 + off);
        ulonglong2 v2 = *reinterpret_cast<const ulonglong2*>(svp2 + off);
        #pragma unroll
        for (int r = 0; r < RPW; r++) {
            acc[r][0] = ffma2(tv[r].x, v0.x, acc[r][0]);
            acc[r][0] = ffma2(tv[r].y, v0.y, acc[r][0]);
            acc[r][1] = ffma2(tv[r].x, v1.x, acc[r][1]);
            acc[r][1] = ffma2(tv[r].y, v1.y, acc[r][1]);
            acc[r][2] = ffma2(tv[r].x, v2.x, acc[r][2]);
            acc[r][2] = ffma2(tv[r].y, v2.y, acc[r][2]);
            nrm[r]    = ffma2(tv[r].x, tv[r].x, nrm[r]);
            nrm[r]    = ffma2(tv[r].y, tv[r].y, nrm[r]);
        }
        if (s < 15) {
            #pragma unroll
            for (int r = 0; r < RPW; r++) tv[r] = tnx[r];
        }
    }

    // ---- reduction tail: once per warp, 5 independent row chains ----
    float wcmin = 1e30f, wcmax = -1e30f;
    #pragma unroll
    for (int r = 0; r < RPW; r++) {
        float d0 = hsum2(acc[r][0]);
        float d1 = hsum2(acc[r][1]);
        float d2 = hsum2(acc[r][2]);
        float ns = hsum2(nrm[r]);
        #pragma unroll
        for (int o = 1; o <= 4; o <<= 1) {                 // reduce across 8 d-lanes
            d0 += __shfl_xor_sync(0xffffffffu, d0, o);
            d1 += __shfl_xor_sync(0xffffffffu, d1, o);
            d2 += __shfl_xor_sync(0xffffffffu, d2, o);
            ns += __shfl_xor_sync(0xffffffffu, ns, o);
        }
        float rin = rsqrtf(ns);
        float c0 = d0 * rin * vinv0;
        float c1 = d1 * rin * vinv1;
        float c2 = d2 * rin * vinv2;
        float cmn = fminf(c0, fminf(c1, c2));
        float cmx = fmaxf(c0, fmaxf(c1, c2));
        cmn = fminf(cmn, __shfl_xor_sync(0xffffffffu, cmn, 8));
        cmn = fminf(cmn, __shfl_xor_sync(0xffffffffu, cmn, 16));
        cmx = fmaxf(cmx, __shfl_xor_sync(0xffffffffu, cmx, 8));
        cmx = fmaxf(cmx, __shfl_xor_sync(0xffffffffu, cmx, 16));
        wcmin = fminf(wcmin, cmn);
        wcmax = fmaxf(wcmax, cmx);
    }

    if (lane == 0) { s_wmin[warp] = wcmin; s_wmax[warp] = wcmax; }
    __syncthreads();
    if (tid == 0) {
        float mn = s_wmin[0], mx = s_wmax[0];
        #pragma unroll
        for (int w = 1; w < 8; w++) {
            mn = fminf(mn, s_wmin[w]);
            mx = fmaxf(mx, s_wmax[w]);
        }
        g_part_min[blockIdx.x] = mn;   // min cos (chunk partial)
        g_part_max[blockIdx.x] = mx;   // max cos (chunk partial)
        __threadfence();
        unsigned int v = atomicAdd(&g_done, 1u);
        s_last = (v == gridDim.x - 1) ? 1u : 0u;
    }
    __syncthreads();

    // ---- last CTA: reduce all partials once, emit rv/dv arrays ----
    if (s_last) {
        const int n = gridDim.x;
        float cmn = 1e30f, cmx = -1e30f;
        for (int j = tid; j < n; j += THREADS) {
            cmn = fminf(cmn, g_part_min[j]);
            cmx = fmaxf(cmx, g_part_max[j]);
        }
        red_mn[tid] = cmn; red_mx[tid] = cmx;
        __syncthreads();
        #pragma unroll
        for (int o = 128; o > 0; o >>= 1) {
            if (tid < o) {
                red_mn[tid] = fminf(red_mn[tid], red_mn[tid + o]);
                red_mx[tid] = fmaxf(red_mx[tid], red_mx[tid + o]);
            }
            __syncthreads();
        }
        const float mn  = 1.0f - red_mx[0];          // global min of dis
        const float mx  = 1.0f - red_mn[0];          // global max of dis
        const float inv = 1.0f / (mx - mn);
        const int B = n / chunks;
        for (int i = tid; i < B; i += THREADS) {
            float m0 = 1e30f, m1 = -1e30f;
            for (int c = 0; c < chunks; c++) {
                m0 = fminf(m0, g_part_min[i * chunks + c]);
                m1 = fmaxf(m1, g_part_max[i * chunks + c]);
            }
            g_rowval[i]  = ((1.0f - m0) - mn) * inv;  // off-diagonal (dmax_i)
            g_diagval[i] = ((1.0f - m1) - mn) * inv;  // diagonal (dmin_i)
        }
        __syncthreads();
        if (tid == 0) {
            __threadfence();
            g_done = 0;                                // reset for graph replay
        }
    }
}

// ---------------------------------------------------------------------------
// Kernel 2: trivial fill. One block per row, 128 threads, 1 STG.128 each.
// ---------------------------------------------------------------------------
__global__ void fill_kernel(float* __restrict__ out, int B)
{
    const int i  = blockIdx.x;
    const float rv = __ldg(&g_rowval[i]);
    const float dv = __ldg(&g_diagval[i]);
    const int c  = threadIdx.x;                 // B/4 = 128 float4 per row
    float4 v = make_float4(rv, rv, rv, rv);
    if (c == (i >> 2)) reinterpret_cast<float*>(&v)[i & 3] = dv;
    reinterpret_cast<float4*>(out + (size_t)i * B)[c] = v;
}

// ---------------------------------------------------------------------------
extern "C" void kernel_launch(void* const* d_in, const int* in_sizes, int n_in,
                              void* d_out, int out_size)
{
    const float* text  = (const float*)d_in[0];   // [B, T, D] fp32
    const float* video = (const float*)d_in[1];   // [B, F, D] fp32
    float* out = (float*)d_out;                   // [B, B] fp32

    const int B = in_sizes[1] / (FV * D);
    const int T = in_sizes[0] / (B * D);
    const int chunks = (T + ROWS_CTA - 1) / ROWS_CTA;   // 2 for T=77

    sample_minmax_kernel<<<B * chunks, THREADS>>>(text, video, T, chunks);
    fill_kernel<<<B, 128>>>(out, B);
}

// round 9
// speedup vs baseline: 1.0257x; 1.0257x over previous
#include <cuda_runtime.h>
#include <cstdint>
#include <cstddef>

#define DEV_INLINE __device__ __forceinline__

constexpr int D        = 512;       // feature dim
constexpr int FV       = 12;        // video frames
constexpr int THREADS  = 256;       // 8 warps
constexpr int RPW      = 5;         // text rows per warp (single pass)
constexpr int ROWS_CTA = 8 * RPW;   // 40 rows per item
constexpr int GRID     = 296;       // 2 CTAs x 148 SMs, all co-resident

// scratch (allocation-free: __device__ globals)
__device__ float g_part_min[4096];
__device__ float g_part_max[4096];
__device__ unsigned int g_ticket = 0;
__device__ unsigned int g_arrive = 0;
__device__ unsigned int g_exit   = 0;

DEV_INLINE unsigned long long ffma2(unsigned long long a, unsigned long long b,
                                    unsigned long long c) {
    unsigned long long d;
    asm("fma.rn.f32x2 %0, %1, %2, %3;" : "=l"(d) : "l"(a), "l"(b), "l"(c));
    return d;
}

DEV_INLINE float hsum2(unsigned long long v) {
    float lo, hi;
    asm("mov.b64 {%0, %1}, %2;" : "=f"(lo), "=f"(hi) : "l"(v));
    return lo + hi;
}

DEV_INLINE void cp_async16(uint32_t smem_addr, const void* gptr) {
    asm volatile("cp.async.cg.shared.global [%0], [%1], 16;"
                 :: "r"(smem_addr), "l"(gptr));
}
#define CP_COMMIT()  asm volatile("cp.async.commit_group;")
#define CP_WAIT0()   asm volatile("cp.async.wait_group 0;" ::: "memory")

// ---------------------------------------------------------------------------
// Single persistent kernel.
// Phase 1: CTAs pull (sample,chunk) items off an atomic ticket queue; per item:
//   video (24KB) staged via cp.async, text read via LDG.128 + 1-step prefetch,
//   min/max cosine over (40 text rows) x (12 frames) -> partials.
// Phase 2: device-side grid barrier (all 296 CTAs resident by construction),
//   every CTA redundantly reduces the partials (L2-resident) to the global
//   min/max, then cooperatively writes the BxB output.
// Counters reset by the last CTA -> graph-replay deterministic.
// ---------------------------------------------------------------------------
__global__ void __launch_bounds__(THREADS, 2)
distance_persistent_kernel(const float* __restrict__ text,
                           const float* __restrict__ video,
                           float* __restrict__ out,
                           int T, int B, int chunks)
{
    __shared__ float sv[FV * D];          // 24 KB video tile
    __shared__ float s_vinv[FV];
    __shared__ float s_wmin[8], s_wmax[8];
    __shared__ float red_mn[THREADS], red_mx[THREADS];
    __shared__ unsigned int s_item;

    const int tid  = threadIdx.x;
    const int warp = tid >> 5;
    const int lane = tid & 31;
    const int fg   = lane >> 3;    // 0..3 : which group of 3 video rows
    const int dl   = lane & 7;     // 0..7 : which slice of D
    const int n_items = B * chunks;

    // ================= Phase 1: item loop =================
    for (;;) {
        if (tid == 0) s_item = atomicAdd(&g_ticket, 1u);
        __syncthreads();
        const unsigned int item = s_item;
        if (item >= (unsigned int)n_items) break;

        const int b     = item / chunks;
        const int chunk = item % chunks;
        const char*  vsrc = reinterpret_cast<const char*>(video + (size_t)b * FV * D);
        const float* tb   = text + (size_t)b * (size_t)T * D;
        const int    base = chunk * ROWS_CTA;

        // ---- issue video staging (one cp.async group) ----
        {
            uint32_t svb = (uint32_t)__cvta_generic_to_shared(sv);
            #pragma unroll
            for (int i = tid; i < FV * (D / 4); i += THREADS)
                cp_async16(svb + i * 16, vsrc + i * 16);
            CP_COMMIT();
        }

        // ---- text row pointers (clamped duplicates harmless for min/max) ----
        const float* trp[RPW];
        #pragma unroll
        for (int r = 0; r < RPW; r++) {
            int tt = base + warp * RPW + r; if (tt > T - 1) tt = T - 1;
            trp[r] = tb + (size_t)tt * D;
        }

        // ---- prime step-0 text loads (hidden behind the norm phase) ----
        ulonglong2 tv[RPW];
        #pragma unroll
        for (int r = 0; r < RPW; r++)
            tv[r] = *reinterpret_cast<const ulonglong2*>(trp[r] + dl * 4);

        CP_WAIT0();
        __syncthreads();

        // ---- inverse norms of the 12 video rows (from shared) ----
        for (int f = warp; f < FV; f += 8) {
            float s = 0.f;
            #pragma unroll
            for (int c = lane; c < D / 4; c += 32) {
                float4 x = *reinterpret_cast<const float4*>(&sv[f * D + c * 4]);
                s += x.x * x.x + x.y * x.y + x.z * x.z + x.w * x.w;
            }
            #pragma unroll
            for (int o = 16; o > 0; o >>= 1) s += __shfl_xor_sync(0xffffffffu, s, o);
            if (lane == 0) s_vinv[f] = rsqrtf(s);
        }
        __syncthreads();

        const int f0 = fg * 3;
        const float vinv0 = s_vinv[f0 + 0];
        const float vinv1 = s_vinv[f0 + 1];
        const float vinv2 = s_vinv[f0 + 2];
        const float* svp0 = &sv[(f0 + 0) * D];
        const float* svp1 = &sv[(f0 + 1) * D];
        const float* svp2 = &sv[(f0 + 2) * D];

        unsigned long long acc[RPW][3];
        unsigned long long nrm[RPW];
        #pragma unroll
        for (int r = 0; r < RPW; r++) {
            acc[r][0] = 0ull; acc[r][1] = 0ull; acc[r][2] = 0ull; nrm[r] = 0ull;
        }

        // ---- mainloop: video from shared, text from global (1-step prefetch) ----
        #pragma unroll
        for (int s = 0; s < 16; s++) {
            const int off = (dl + 8 * s) * 4;
            ulonglong2 tnx[RPW];
            if (s < 15) {
                const int noff = (dl + 8 * (s + 1)) * 4;
                #pragma unroll
                for (int r = 0; r < RPW; r++)
                    tnx[r] = *reinterpret_cast<const ulonglong2*>(trp[r] + noff);
            }
            ulonglong2 v0 = *reinterpret_cast<const ulonglong2*>(svp0 + off);
            ulonglong2 v1 = *reinterpret_cast<const ulonglong2*>(svp1 + off);
            ulonglong2 v2 = *reinterpret_cast<const ulonglong2*>(svp2 + off);
            #pragma unroll
            for (int r = 0; r < RPW; r++) {
                acc[r][0] = ffma2(tv[r].x, v0.x, acc[r][0]);
                acc[r][0] = ffma2(tv[r].y, v0.y, acc[r][0]);
                acc[r][1] = ffma2(tv[r].x, v1.x, acc[r][1]);
                acc[r][1] = ffma2(tv[r].y, v1.y, acc[r][1]);
                acc[r][2] = ffma2(tv[r].x, v2.x, acc[r][2]);
                acc[r][2] = ffma2(tv[r].y, v2.y, acc[r][2]);
                nrm[r]    = ffma2(tv[r].x, tv[r].x, nrm[r]);
                nrm[r]    = ffma2(tv[r].y, tv[r].y, nrm[r]);
            }
            if (s < 15) {
                #pragma unroll
                for (int r = 0; r < RPW; r++) tv[r] = tnx[r];
            }
        }

        // ---- reduction tail ----
        float wcmin = 1e30f, wcmax = -1e30f;
        #pragma unroll
        for (int r = 0; r < RPW; r++) {
            float d0 = hsum2(acc[r][0]);
            float d1 = hsum2(acc[r][1]);
            float d2 = hsum2(acc[r][2]);
            float ns = hsum2(nrm[r]);
            #pragma unroll
            for (int o = 1; o <= 4; o <<= 1) {
                d0 += __shfl_xor_sync(0xffffffffu, d0, o);
                d1 += __shfl_xor_sync(0xffffffffu, d1, o);
                d2 += __shfl_xor_sync(0xffffffffu, d2, o);
                ns += __shfl_xor_sync(0xffffffffu, ns, o);
            }
            float rin = rsqrtf(ns);
            float c0 = d0 * rin * vinv0;
            float c1 = d1 * rin * vinv1;
            float c2 = d2 * rin * vinv2;
            float cmn = fminf(c0, fminf(c1, c2));
            float cmx = fmaxf(c0, fmaxf(c1, c2));
            cmn = fminf(cmn, __shfl_xor_sync(0xffffffffu, cmn, 8));
            cmn = fminf(cmn, __shfl_xor_sync(0xffffffffu, cmn, 16));
            cmx = fmaxf(cmx, __shfl_xor_sync(0xffffffffu, cmx, 8));
            cmx = fmaxf(cmx, __shfl_xor_sync(0xffffffffu, cmx, 16));
            wcmin = fminf(wcmin, cmn);
            wcmax = fmaxf(wcmax, cmx);
        }

        if (lane == 0) { s_wmin[warp] = wcmin; s_wmax[warp] = wcmax; }
        __syncthreads();
        if (tid == 0) {
            float mn = s_wmin[0], mx = s_wmax[0];
            #pragma unroll
            for (int w = 1; w < 8; w++) {
                mn = fminf(mn, s_wmin[w]);
                mx = fmaxf(mx, s_wmax[w]);
            }
            g_part_min[item] = mn;
            g_part_max[item] = mx;
        }
        __syncthreads();   // protect sv/s_vinv before next item's staging
    }

    // ================= grid barrier (all CTAs resident) =================
    if (tid == 0) {
        __threadfence();                       // publish partials (once per CTA)
        atomicAdd(&g_arrive, 1u);
        while (atomicAdd(&g_arrive, 0u) < (unsigned int)gridDim.x)
            __nanosleep(64);
    }
    __syncthreads();

    // ================= Phase 2: reduce + fill =================
    {
        float cmn = 1e30f, cmx = -1e30f;
        for (int j = tid; j < n_items; j += THREADS) {
            cmn = fminf(cmn, g_part_min[j]);
            cmx = fmaxf(cmx, g_part_max[j]);
        }
        red_mn[tid] = cmn; red_mx[tid] = cmx;
        __syncthreads();
        #pragma unroll
        for (int o = THREADS / 2; o > 0; o >>= 1) {
            if (tid < o) {
                red_mn[tid] = fminf(red_mn[tid], red_mn[tid + o]);
                red_mx[tid] = fmaxf(red_mx[tid], red_mx[tid + o]);
            }
            __syncthreads();
        }
        const float mn  = 1.0f - red_mx[0];     // global min of dis
        const float mx  = 1.0f - red_mn[0];     // global max of dis
        const float inv = 1.0f / (mx - mn);

        for (int i = blockIdx.x; i < B; i += gridDim.x) {
            float m0 = 1e30f, m1 = -1e30f;
            for (int c = 0; c < chunks; c++) {
                m0 = fminf(m0, g_part_min[i * chunks + c]);
                m1 = fmaxf(m1, g_part_max[i * chunks + c]);
            }
            const float rv = ((1.0f - m0) - mn) * inv;   // off-diagonal (dmax_i)
            const float dv = ((1.0f - m1) - mn) * inv;   // diagonal (dmin_i)
            float4* orow = reinterpret_cast<float4*>(out + (size_t)i * B);
            const int n4 = B >> 2;
            for (int c = tid; c < n4; c += THREADS) {
                float4 v = make_float4(rv, rv, rv, rv);
                if (c == (i >> 2)) reinterpret_cast<float*>(&v)[i & 3] = dv;
                orow[c] = v;
            }
        }
    }

    // ---- reset counters for the next graph replay ----
    __syncthreads();
    if (tid == 0) {
        unsigned int v = atomicAdd(&g_exit, 1u);
        if (v == gridDim.x - 1) {
            g_ticket = 0;
            g_arrive = 0;
            g_exit   = 0;
            __threadfence();
        }
    }
}

// ---------------------------------------------------------------------------
extern "C" void kernel_launch(void* const* d_in, const int* in_sizes, int n_in,
                              void* d_out, int out_size)
{
    const float* text  = (const float*)d_in[0];   // [B, T, D] fp32
    const float* video = (const float*)d_in[1];   // [B, F, D] fp32
    float* out = (float*)d_out;                   // [B, B] fp32

    const int B = in_sizes[1] / (FV * D);
    const int T = in_sizes[0] / (B * D);
    const int chunks = (T + ROWS_CTA - 1) / ROWS_CTA;   // 2 for T=77

    distance_persistent_kernel<<<GRID, THREADS>>>(text, video, out, T, B, chunks);
}